// round 10
// baseline (speedup 1.0000x reference)
#include <cuda_runtime.h>
#include <math.h>

#define B_     64
#define S_EN_  50
#define S_DE_  50
#define H_     32
#define EMB_E_ 64
#define EMB_D_ 32
#define DE_V_  19000
#define VPB    128
#define NBLK   148
#define MAINV  (NBLK * VPB)          // 18944
#define XCOLS  (DE_V_ - MAINV)       // 56 extra columns -> blocks 0..55
#define NTH    256

// ---------------- device-global scratch ----------------
__device__ unsigned long long g_part[B_][160];          // per-row per-block argmax keys
__device__ __align__(16) unsigned long long g_h2[H_ * B_]; // (h,h) packed, [k][b]
__device__ unsigned g_dc[S_DE_][8];                     // per-step sharded GEMM-done counters (5 used)
__device__ unsigned g_hc[S_DE_ + 1][8];                 // per-step sharded h-ready counters (4 used)
__device__ unsigned g_cnt = 0, g_gen = 0;               // init barrier only

// ---------------- helpers ----------------
__device__ __forceinline__ unsigned long long pack2(float lo, float hi) {
    unsigned long long r;
    asm("mov.b64 %0, {%1, %2};" : "=l"(r) : "f"(lo), "f"(hi));
    return r;
}
__device__ __forceinline__ float2 unpack2(unsigned long long v) {
    float2 r;
    asm("mov.b64 {%0, %1}, %2;" : "=f"(r.x), "=f"(r.y) : "l"(v));
    return r;
}
__device__ __forceinline__ void fma2(unsigned long long& d, unsigned long long a, unsigned long long b) {
    asm("fma.rn.f32x2 %0, %1, %2, %0;" : "+l"(d) : "l"(a), "l"(b));
}
__device__ __forceinline__ float sigmoidf_(float x) { return 1.0f / (1.0f + expf(-x)); }

// larger key == (bigger value, then smaller index) -> matches jnp.argmax
__device__ __forceinline__ unsigned long long amax_key(float f, int v) {
    unsigned u = __float_as_uint(f);
    u = (u & 0x80000000u) ? ~u : (u | 0x80000000u);
    return ((unsigned long long)u << 32) | (unsigned long long)(0xFFFFFFFFu - (unsigned)v);
}
__device__ __forceinline__ unsigned ld_rlx(const unsigned* p) {
    unsigned v;
    asm volatile("ld.relaxed.gpu.global.u32 %0, [%1];" : "=r"(v) : "l"(p) : "memory");
    return v;
}
__device__ __forceinline__ void red_add_rel(unsigned* p, unsigned v) {
    asm volatile("red.release.gpu.global.add.u32 [%0], %1;" :: "l"(p), "r"(v) : "memory");
}
__device__ __forceinline__ void fence_ar() {
    asm volatile("fence.acq_rel.gpu;" ::: "memory");
}

// one-time init barrier (replay-safe)
__device__ __forceinline__ void grid_barrier() {
    __threadfence();
    __syncthreads();
    if (threadIdx.x == 0) {
        unsigned my = *(volatile unsigned*)&g_gen;
        __threadfence();
        if (atomicAdd(&g_cnt, 1u) == NBLK - 1) {
            g_cnt = 0;
            __threadfence();
            atomicAdd(&g_gen, 1u);
        } else {
            while (*(volatile unsigned*)&g_gen == my) { __nanosleep(32); }
        }
    }
    __syncthreads();
}

__global__ void __launch_bounds__(NTH, 1)
seq2seq_kernel(const int* __restrict__ en_batch, const int* __restrict__ en_lens,
               const int* __restrict__ de_batch,
               const float* __restrict__ en_emb,
               const float* __restrict__ eWih, const float* __restrict__ eWhh,
               const float* __restrict__ ebih, const float* __restrict__ ebhh,
               const float* __restrict__ de_emb,
               const float* __restrict__ dWih, const float* __restrict__ dWhh,
               const float* __restrict__ dbih, const float* __restrict__ dbhh,
               const float* __restrict__ fcW, const float* __restrict__ fcb,
               float* __restrict__ out)
{
    __shared__ __align__(16) float sW[H_][VPB];              // fc_W tile [k][v-local]
    __shared__ unsigned long long sWb2[VPB / 2];             // fc_b pairs
    __shared__ __align__(16) unsigned long long sH2[H_][B_]; // (h,h) packed [k][b]
    __shared__ unsigned long long sRedW[8][B_];              // per-warp per-row argmax partials
    __shared__ float sPart[2][4 * H_];
    __shared__ float sBias[4 * H_];
    __shared__ float sX[EMB_E_];
    __shared__ float sWx[H_];                                // extra-column weights
    __shared__ float s_h[H_], s_c[H_];
    __shared__ int   sToks[S_EN_];
    __shared__ int   s_tok;

    const int tid  = threadIdx.x;
    const int bk   = blockIdx.x;
    const int v0   = bk * VPB;
    const int jg   = tid & 127;     // gate index
    const int hf   = tid >> 7;      // half selector
    const int wid  = tid >> 5;
    const int lane = tid & 31;
    const bool has_x = (bk < XCOLS);
    const int  xcol  = MAINV + bk;

    // ---------- phase 0: zero out[:,0,:], zero sync state ----------
    for (int i = tid; i < B_ * VPB; i += NTH) {
        int b = i / VPB, v = i % VPB;
        out[(size_t)(b * S_DE_) * DE_V_ + v0 + v] = 0.0f;
    }
    if (has_x && tid < B_) out[(size_t)(tid * S_DE_) * DE_V_ + xcol] = 0.0f;
    {
        int gt = bk * NTH + tid;
        if (gt < S_DE_ * 8)       (&g_dc[0][0])[gt] = 0u;
        if (gt < (S_DE_ + 1) * 8) (&g_hc[0][0])[gt] = 0u;
    }

    // ---------- fc tile into smem ----------
    for (int i = tid; i < H_ * VPB; i += NTH) {
        int v = i >> 5, k = i & 31;
        sW[k][v] = fcW[(size_t)(v0 + v) * H_ + k];
    }
    for (int i = tid; i < VPB / 2; i += NTH)
        sWb2[i] = pack2(fcb[v0 + 2 * i], fcb[v0 + 2 * i + 1]);
    float bxv = 0.0f;
    if (has_x) {
        if (tid < H_) sWx[tid] = fcW[(size_t)xcol * H_ + tid];
        bxv = fcb[xcol];
    }

    grid_barrier();     // zeroed counters visible chip-wide before any arrive/poll

    float wreg[48];

    // ---------- encoder + first decoder LSTM: blocks 0..63 ----------
    if (bk < B_) {
        #pragma unroll
        for (int k = 0; k < 32; k++) wreg[k] = eWih[jg * EMB_E_ + hf * 32 + k];
        #pragma unroll
        for (int k = 0; k < 16; k++) wreg[32 + k] = eWhh[jg * H_ + hf * 16 + k];
        if (tid < 4 * H_) sBias[tid] = ebih[tid] + ebhh[tid];
        if (tid < H_) { s_h[tid] = 0.0f; s_c[tid] = 0.0f; }
        if (tid < S_EN_) sToks[tid] = en_batch[bk * S_EN_ + tid];
        __syncthreads();

        const int len = en_lens[bk];
        float xr = 0.0f;
        if (tid < EMB_E_ && len > 0) xr = en_emb[(size_t)sToks[0] * EMB_E_ + tid];
        for (int t = 0; t < len; t++) {
            if (tid < EMB_E_) sX[tid] = xr;
            __syncthreads();
            if (tid < EMB_E_ && t + 1 < len)                   // prefetch next emb
                xr = en_emb[(size_t)sToks[t + 1] * EMB_E_ + tid];
            {
                float p = 0.0f;
                #pragma unroll
                for (int k = 0; k < 32; k++) p += sX[hf * 32 + k] * wreg[k];
                #pragma unroll
                for (int k = 0; k < 16; k++) p += s_h[hf * 16 + k] * wreg[32 + k];
                sPart[hf][jg] = p;
            }
            __syncthreads();
            if (tid < H_) {
                float gi = sPart[0][tid]          + sPart[1][tid]          + sBias[tid];
                float gf = sPart[0][H_ + tid]     + sPart[1][H_ + tid]     + sBias[H_ + tid];
                float gg = sPart[0][2 * H_ + tid] + sPart[1][2 * H_ + tid] + sBias[2 * H_ + tid];
                float go = sPart[0][3 * H_ + tid] + sPart[1][3 * H_ + tid] + sBias[3 * H_ + tid];
                float ig = sigmoidf_(gi), fg = sigmoidf_(gf), og = sigmoidf_(go);
                float c  = fg * s_c[tid] + ig * tanhf(gg);
                s_c[tid] = c;
                s_h[tid] = og * tanhf(c);
            }
            __syncthreads();
        }

        // decoder weights: hf0 threads own Wih row, hf1 threads own Whh row
        #pragma unroll
        for (int k = 0; k < 32; k++)
            wreg[k] = hf ? dWhh[jg * H_ + k] : dWih[jg * EMB_D_ + k];
        if (tid < 4 * H_) sBias[tid] = dbih[tid] + dbhh[tid];
        __syncthreads();

        // first decoder step
        {
            int tok = de_batch[bk * S_DE_];
            if (tid < EMB_D_) sX[tid] = de_emb[(size_t)tok * EMB_D_ + tid];
            __syncthreads();
            {
                const float* src = hf ? s_h : sX;
                float p = 0.0f;
                #pragma unroll
                for (int k = 0; k < 32; k++) p += src[k] * wreg[k];
                sPart[hf][jg] = p;
            }
            __syncthreads();
            if (tid < H_) {
                float gi = sPart[0][tid]          + sPart[1][tid]          + sBias[tid];
                float gf = sPart[0][H_ + tid]     + sPart[1][H_ + tid]     + sBias[H_ + tid];
                float gg = sPart[0][2 * H_ + tid] + sPart[1][2 * H_ + tid] + sBias[2 * H_ + tid];
                float go = sPart[0][3 * H_ + tid] + sPart[1][3 * H_ + tid] + sBias[3 * H_ + tid];
                float ig = sigmoidf_(gi), fg = sigmoidf_(gf), og = sigmoidf_(go);
                float c  = fg * s_c[tid] + ig * tanhf(gg);
                s_c[tid] = c;
                float h  = og * tanhf(c);
                s_h[tid] = h;
                __stcg(&g_h2[tid * B_ + bk], pack2(h, h));
            }
            __syncwarp();
            if (tid == 0) red_add_rel(&g_hc[1][bk >> 4], 1u);
            __syncthreads();
            if (hf == 1) {          // precompute Whh·h for next step
                float p = 0.0f;
                #pragma unroll
                for (int k = 0; k < 32; k++) p += s_h[k] * wreg[k];
                sPart[1][jg] = p;
            }
        }
    }

    const int bq  = tid & 15;       // b-lane
    const int vq  = tid >> 4;       // v-octet
    const int vl0 = vq * 8;

    for (int s = 1; s < S_DE_; s++) {
        // ---------- wait for h_s (4 sharded counters of 16), copy packed h ----------
        if (tid == 0) {
            for (;;) {
                unsigned a = ld_rlx(&g_hc[s][0]), b = ld_rlx(&g_hc[s][1]);
                unsigned c = ld_rlx(&g_hc[s][2]), d = ld_rlx(&g_hc[s][3]);
                if ((a & b & c & d) == 16u && a + b + c + d == 64u) break;
            }
            fence_ar();
        }
        __syncthreads();
        {
            const uint4* src = (const uint4*)g_h2;
            uint4* dst = (uint4*)&sH2[0][0];
            #pragma unroll
            for (int r = 0; r < 4; r++) dst[tid + NTH * r] = __ldcg(&src[tid + NTH * r]);
        }
        __syncthreads();

        // ---------- logits tile ----------
        unsigned long long acc[4][4];
        #pragma unroll
        for (int i = 0; i < 4; i++)
            #pragma unroll
            for (int j = 0; j < 4; j++) acc[i][j] = sWb2[vq * 4 + j];

        #pragma unroll 8
        for (int k = 0; k < H_; k++) {
            const unsigned long long* w64 = (const unsigned long long*)&sW[k][0];
            unsigned long long w0 = w64[vq * 4 + 0];
            unsigned long long w1 = w64[vq * 4 + 1];
            unsigned long long w2 = w64[vq * 4 + 2];
            unsigned long long w3 = w64[vq * 4 + 3];
            #pragma unroll
            for (int i = 0; i < 4; i++) {
                unsigned long long hh = sH2[k][bq + 16 * i];
                fma2(acc[i][0], hh, w0);
                fma2(acc[i][1], hh, w1);
                fma2(acc[i][2], hh, w2);
                fma2(acc[i][3], hh, w3);
            }
        }

        const bool last = (s == S_DE_ - 1);

        // ---------- extra column (blocks 0..55), thread tid == row ----------
        float xdot = 0.0f;
        if (has_x && tid < B_) {
            const float* sH2f = (const float*)&sH2[0][0];
            float p = bxv;
            #pragma unroll
            for (int k = 0; k < H_; k++) p += sH2f[(k * B_ + tid) * 2] * sWx[k];
            xdot = p;
        }

        // ---------- argmax: registers -> shfl -> smem -> own g_part slot ----------
        if (!last) {
            const int vb = v0 + vl0;
            unsigned long long kr[4];
            #pragma unroll
            for (int i = 0; i < 4; i++) {
                float2 p0 = unpack2(acc[i][0]);
                float2 p1 = unpack2(acc[i][1]);
                float2 p2 = unpack2(acc[i][2]);
                float2 p3 = unpack2(acc[i][3]);
                unsigned long long best = amax_key(p0.x, vb);
                unsigned long long k2;
                k2 = amax_key(p0.y, vb + 1); if (k2 > best) best = k2;
                k2 = amax_key(p1.x, vb + 2); if (k2 > best) best = k2;
                k2 = amax_key(p1.y, vb + 3); if (k2 > best) best = k2;
                k2 = amax_key(p2.x, vb + 4); if (k2 > best) best = k2;
                k2 = amax_key(p2.y, vb + 5); if (k2 > best) best = k2;
                k2 = amax_key(p3.x, vb + 6); if (k2 > best) best = k2;
                k2 = amax_key(p3.y, vb + 7); if (k2 > best) best = k2;
                kr[i] = best;
            }
            #pragma unroll
            for (int i = 0; i < 4; i++) {
                unsigned long long o = __shfl_xor_sync(0xffffffffu, kr[i], 16);
                if (o > kr[i]) kr[i] = o;
            }
            if (lane < 16) {
                #pragma unroll
                for (int i = 0; i < 4; i++) sRedW[wid][bq + 16 * i] = kr[i];
            }
            __syncthreads();
            if (tid < B_) {
                unsigned long long best = sRedW[0][tid];
                #pragma unroll
                for (int w = 1; w < 8; w++) { unsigned long long o = sRedW[w][tid]; if (o > best) best = o; }
                if (has_x) { unsigned long long o = amax_key(xdot, xcol); if (o > best) best = o; }
                __stcg(&g_part[tid][bk], best);     // own slot: no contention
            }
            __syncthreads();
            if (tid == 0) {
                fence_ar();                          // drain this block's 64 key stores
                red_add_rel(&g_dc[s][bk >> 5], 1u);  // sharded arrival
            }
        }

        // ---------- bulk logits stores: off the critical path ----------
        #pragma unroll
        for (int i = 0; i < 4; i++) {
            const int b = bq + 16 * i;
            float2 p0 = unpack2(acc[i][0]);
            float2 p1 = unpack2(acc[i][1]);
            float2 p2 = unpack2(acc[i][2]);
            float2 p3 = unpack2(acc[i][3]);
            float4* orow = (float4*)(out + ((size_t)b * S_DE_ + s) * DE_V_ + v0 + vl0);
            __stcs(&orow[0], make_float4(p0.x, p0.y, p1.x, p1.y));
            __stcs(&orow[1], make_float4(p2.x, p2.y, p3.x, p3.y));
        }
        if (has_x && tid < B_)
            __stcs(&out[((size_t)tid * S_DE_ + s) * DE_V_ + xcol], xdot);

        // ---------- LSTM: produce h for step s+1 (blocks 0..63) ----------
        if (!last && bk < B_) {
            if (tid < 32) {
                if (lane == 0) {
                    for (;;) {
                        unsigned a = ld_rlx(&g_dc[s][0]), b = ld_rlx(&g_dc[s][1]);
                        unsigned c = ld_rlx(&g_dc[s][2]), d = ld_rlx(&g_dc[s][3]);
                        unsigned e = ld_rlx(&g_dc[s][4]);
                        if (a + b + c + d + e == (unsigned)NBLK) break;
                    }
                }
                __syncwarp();
                fence_ar();
                // reduce this row's 148 keys with one warp
                unsigned long long best = 0ull;
                #pragma unroll
                for (int j = 0; j < 5; j++) {
                    int idx = lane + 32 * j;
                    if (idx < NBLK) {
                        unsigned long long k = __ldcg(&g_part[bk][idx]);
                        if (k > best) best = k;
                    }
                }
                #pragma unroll
                for (int o = 16; o; o >>= 1) {
                    unsigned long long oth = __shfl_xor_sync(0xffffffffu, best, o);
                    if (oth > best) best = oth;
                }
                if (lane == 0) s_tok = (int)(0xFFFFFFFFu - (unsigned)(best & 0xFFFFFFFFull));
                __syncwarp();
                if (lane < EMB_D_) sX[lane] = de_emb[(size_t)s_tok * EMB_D_ + lane];
            }
            __syncthreads();
            if (hf == 0) {                      // x-part only; h-part precomputed
                float p = 0.0f;
                #pragma unroll
                for (int k = 0; k < 32; k++) p += sX[k] * wreg[k];
                sPart[0][jg] = p;
            }
            __syncthreads();
            if (tid < H_) {
                float gi = sPart[0][tid]          + sPart[1][tid]          + sBias[tid];
                float gf = sPart[0][H_ + tid]     + sPart[1][H_ + tid]     + sBias[H_ + tid];
                float gg = sPart[0][2 * H_ + tid] + sPart[1][2 * H_ + tid] + sBias[2 * H_ + tid];
                float go = sPart[0][3 * H_ + tid] + sPart[1][3 * H_ + tid] + sBias[3 * H_ + tid];
                float ig = sigmoidf_(gi), fg = sigmoidf_(gf), og = sigmoidf_(go);
                float c  = fg * s_c[tid] + ig * tanhf(gg);
                s_c[tid] = c;
                float h  = og * tanhf(c);
                s_h[tid] = h;
                __stcg(&g_h2[tid * B_ + bk], pack2(h, h));
            }
            __syncwarp();
            if (tid == 0) red_add_rel(&g_hc[s + 1][bk >> 4], 1u);
            __syncthreads();
            if (hf == 1) {                      // precompute Whh·h for next step
                float p = 0.0f;
                #pragma unroll
                for (int k = 0; k < 32; k++) p += s_h[k] * wreg[k];
                sPart[1][jg] = p;
            }
        }
    }
}

extern "C" void kernel_launch(void* const* d_in, const int* in_sizes, int n_in,
                              void* d_out, int out_size) {
    const int*   en_batch = (const int*)d_in[0];
    const int*   en_lens  = (const int*)d_in[1];
    const int*   de_batch = (const int*)d_in[2];
    const float* en_emb   = (const float*)d_in[3];
    const float* eWih     = (const float*)d_in[4];
    const float* eWhh     = (const float*)d_in[5];
    const float* ebih     = (const float*)d_in[6];
    const float* ebhh     = (const float*)d_in[7];
    const float* de_emb   = (const float*)d_in[8];
    const float* dWih     = (const float*)d_in[9];
    const float* dWhh     = (const float*)d_in[10];
    const float* dbih     = (const float*)d_in[11];
    const float* dbhh     = (const float*)d_in[12];
    const float* fcW      = (const float*)d_in[13];
    const float* fcb      = (const float*)d_in[14];

    seq2seq_kernel<<<NBLK, NTH>>>(en_batch, en_lens, de_batch, en_emb,
                                  eWih, eWhh, ebih, ebhh,
                                  de_emb, dWih, dWhh, dbih, dbhh,
                                  fcW, fcb, (float*)d_out);
}